// round 1
// baseline (speedup 1.0000x reference)
#include <cuda_runtime.h>

#define QB      32
#define THREADS 256

// ---- packed f32x2 helpers (sm_103a) ----
static __device__ __forceinline__ unsigned long long f32x2_add(unsigned long long a, unsigned long long b) {
    unsigned long long r;
    asm("add.rn.f32x2 %0, %1, %2;" : "=l"(r) : "l"(a), "l"(b));
    return r;
}
static __device__ __forceinline__ unsigned long long f32x2_fma(unsigned long long a, unsigned long long b, unsigned long long c) {
    unsigned long long r;
    asm("fma.rn.f32x2 %0, %1, %2, %3;" : "=l"(r) : "l"(a), "l"(b), "l"(c));
    return r;
}
static __device__ __forceinline__ unsigned long long pack2(float lo, float hi) {
    unsigned long long r;
    asm("mov.b64 %0, {%1, %2};" : "=l"(r) : "f"(lo), "f"(hi));
    return r;
}
static __device__ __forceinline__ unsigned long long abs2(unsigned long long a) {
    return a & 0x7FFFFFFF7FFFFFFFULL;   // clears both sign bits -> 2x LOP3 on alu pipe
}
static __device__ __forceinline__ float lo32(unsigned long long v) { return __uint_as_float((unsigned)v); }
static __device__ __forceinline__ float hi32(unsigned long long v) { return __uint_as_float((unsigned)(v >> 32)); }

// C[bq, t] = 5 * sum_d |qb[bq][d] - tb[t][d]|  -  p_{label[t]}(bq)
// p0 = 1/(1+exp(l1-l0));  cc = -(p0 + lab*(p1-p0)) = fma(lab, 2*p0-1, -p0)
__global__ __launch_bounds__(THREADS)
void hm_cost_kernel(const float* __restrict__ logits,   // [32768, 2]
                    const float* __restrict__ qboxes,   // [32768, 6]
                    const int*   __restrict__ tlabels,  // [1024]
                    const float* __restrict__ tboxes,   // [1024, 6]
                    float*       __restrict__ out)      // [32768, 1024]
{
    __shared__ unsigned long long sq[QB * 8];  // per query: 6 dup'd 5*box dims, dup A, dup Dn

    const int tx = threadIdx.x;
    const int q0 = blockIdx.x * QB;

    // ---- cooperative query preload: 256 threads == 32 queries x 8 fields ----
    {
        const int q = tx >> 3;
        const int f = tx & 7;
        const int gq = q0 + q;
        float x;
        if (f < 6) {
            x = 5.0f * qboxes[gq * 6 + f];
        } else {
            const float l0 = logits[gq * 2 + 0];
            const float l1 = logits[gq * 2 + 1];
            const float p0 = 1.0f / (1.0f + __expf(l1 - l0));
            x = (f == 6) ? -p0 : (2.0f * p0 - 1.0f);
        }
        sq[q * 8 + f] = pack2(x, x);
    }

    // ---- per-thread targets: 4 rows of tgt_boxes, pre-negated & pre-scaled ----
    unsigned long long ntb[2][6];
    unsigned long long lab2[2];
    {
        const float4* tb4 = (const float4*)(tboxes + (size_t)tx * 24);
        const float4 v0 = tb4[0], v1 = tb4[1], v2 = tb4[2];
        const float4 v3 = tb4[3], v4 = tb4[4], v5 = tb4[5];
        const float r0[6] = {v0.x, v0.y, v0.z, v0.w, v1.x, v1.y};
        const float r1[6] = {v1.z, v1.w, v2.x, v2.y, v2.z, v2.w};
        const float r2[6] = {v3.x, v3.y, v3.z, v3.w, v4.x, v4.y};
        const float r3[6] = {v4.z, v4.w, v5.x, v5.y, v5.z, v5.w};
#pragma unroll
        for (int d = 0; d < 6; ++d) {
            ntb[0][d] = pack2(-5.0f * r0[d], -5.0f * r1[d]);
            ntb[1][d] = pack2(-5.0f * r2[d], -5.0f * r3[d]);
        }
        const int4 lb = *(const int4*)(tlabels + tx * 4);
        lab2[0] = pack2((float)lb.x, (float)lb.y);
        lab2[1] = pack2((float)lb.z, (float)lb.w);
    }
    __syncthreads();

    // ---- main loop over the block's queries ----
    float4* obase = (float4*)out;
#pragma unroll 4
    for (int q = 0; q < QB; ++q) {
        const unsigned long long* qq = &sq[q * 8];
        const unsigned long long b0 = qq[0], b1 = qq[1], b2 = qq[2];
        const unsigned long long b3 = qq[3], b4 = qq[4], b5 = qq[5];
        const unsigned long long A2 = qq[6], Dn2 = qq[7];

        float4 res;
#pragma unroll
        for (int p = 0; p < 2; ++p) {
            const unsigned long long a0 = abs2(f32x2_add(b0, ntb[p][0]));
            const unsigned long long a1 = abs2(f32x2_add(b1, ntb[p][1]));
            const unsigned long long a2 = abs2(f32x2_add(b2, ntb[p][2]));
            const unsigned long long a3 = abs2(f32x2_add(b3, ntb[p][3]));
            const unsigned long long a4 = abs2(f32x2_add(b4, ntb[p][4]));
            const unsigned long long a5 = abs2(f32x2_add(b5, ntb[p][5]));
            const unsigned long long s  =
                f32x2_add(f32x2_add(f32x2_add(a0, a1), f32x2_add(a2, a3)),
                          f32x2_add(a4, a5));
            const unsigned long long cc = f32x2_fma(lab2[p], Dn2, A2);
            const unsigned long long o  = f32x2_add(s, cc);
            if (p == 0) { res.x = lo32(o); res.y = hi32(o); }
            else        { res.z = lo32(o); res.w = hi32(o); }
        }
        obase[((size_t)(q0 + q) * 1024 + 4 * tx) >> 2] = res;
    }
}

extern "C" void kernel_launch(void* const* d_in, const int* in_sizes, int n_in,
                              void* d_out, int out_size)
{
    const float* logits  = (const float*)d_in[0];  // (16, 2048, 2) f32
    const float* qboxes  = (const float*)d_in[1];  // (16, 2048, 6) f32
    const int*   tlabels = (const int*)  d_in[2];  // (1024,) int (jax x64-off => int32)
    const float* tboxes  = (const float*)d_in[3];  // (1024, 6) f32

    const int total_q = 16 * 2048;
    hm_cost_kernel<<<total_q / QB, THREADS>>>(logits, qboxes, tlabels, tboxes, (float*)d_out);
}

// round 2
// speedup vs baseline: 1.0118x; 1.0118x over previous
#include <cuda_runtime.h>

#define QB      32
#define THREADS 256

// ---- packed f32x2 helpers (sm_103a) ----
static __device__ __forceinline__ unsigned long long f32x2_add(unsigned long long a, unsigned long long b) {
    unsigned long long r;
    asm("add.rn.f32x2 %0, %1, %2;" : "=l"(r) : "l"(a), "l"(b));
    return r;
}
static __device__ __forceinline__ unsigned long long f32x2_fma(unsigned long long a, unsigned long long b, unsigned long long c) {
    unsigned long long r;
    asm("fma.rn.f32x2 %0, %1, %2, %3;" : "=l"(r) : "l"(a), "l"(b), "l"(c));
    return r;
}
static __device__ __forceinline__ unsigned long long pack2(float lo, float hi) {
    unsigned long long r;
    asm("mov.b64 %0, {%1, %2};" : "=l"(r) : "f"(lo), "f"(hi));
    return r;
}
static __device__ __forceinline__ unsigned long long abs2(unsigned long long a) {
    return a & 0x7FFFFFFF7FFFFFFFULL;   // 2x LOP3 on alu pipe (parallel to fma pipe)
}

// C[bq, t] = 5 * sum_d |qb[bq][d] - tb[t][d]|  -  p_{label[t]}(bq)
// p0 = 1/(1+exp(l1-l0));  cc = fma(lab, 2*p0-1, -p0)
__global__ __launch_bounds__(THREADS)
void hm_cost_kernel(const float* __restrict__ logits,   // [32768, 2]
                    const float* __restrict__ qboxes,   // [32768, 6]
                    const int*   __restrict__ tlabels,  // [1024]
                    const float* __restrict__ tboxes,   // [1024, 6]
                    float*       __restrict__ out)      // [32768, 1024]
{
    // per query: 6 dup'd (5*box) dims, dup A, dup Dn  -> 8 ulls = 4x LDS.128
    __shared__ __align__(16) unsigned long long sq[QB * 8];

    const int tx = threadIdx.x;
    const int q0 = blockIdx.x * QB;

    // ---- cooperative query preload: 256 threads == 32 queries x 8 fields ----
    {
        const int q = tx >> 3;
        const int f = tx & 7;
        const int gq = q0 + q;
        float x;
        if (f < 6) {
            x = 5.0f * qboxes[gq * 6 + f];
        } else {
            const float l0 = logits[gq * 2 + 0];
            const float l1 = logits[gq * 2 + 1];
            const float p0 = 1.0f / (1.0f + __expf(l1 - l0));
            x = (f == 6) ? -p0 : (2.0f * p0 - 1.0f);
        }
        sq[q * 8 + f] = pack2(x, x);
    }

    // ---- per-thread targets: 4 rows of tgt_boxes, pre-negated & pre-scaled ----
    unsigned long long ntb[2][6];
    unsigned long long lab2[2];
    {
        const float4* tb4 = (const float4*)(tboxes + (size_t)tx * 24);
        const float4 v0 = tb4[0], v1 = tb4[1], v2 = tb4[2];
        const float4 v3 = tb4[3], v4 = tb4[4], v5 = tb4[5];
        const float r0[6] = {v0.x, v0.y, v0.z, v0.w, v1.x, v1.y};
        const float r1[6] = {v1.z, v1.w, v2.x, v2.y, v2.z, v2.w};
        const float r2[6] = {v3.x, v3.y, v3.z, v3.w, v4.x, v4.y};
        const float r3[6] = {v4.z, v4.w, v5.x, v5.y, v5.z, v5.w};
#pragma unroll
        for (int d = 0; d < 6; ++d) {
            ntb[0][d] = pack2(-5.0f * r0[d], -5.0f * r1[d]);
            ntb[1][d] = pack2(-5.0f * r2[d], -5.0f * r3[d]);
        }
        const int4 lb = *(const int4*)(tlabels + tx * 4);
        lab2[0] = pack2((float)lb.x, (float)lb.y);
        lab2[1] = pack2((float)lb.z, (float)lb.w);
    }
    __syncthreads();

    // ---- main loop: per-thread base pointer, per-q stores at [base + q*4096] ----
    char* obase = (char*)out + ((size_t)q0 * 1024 + 4 * tx) * sizeof(float);

#pragma unroll 8
    for (int q = 0; q < QB; ++q) {
        // 4x LDS.128 (broadcast, conflict-free)
        const ulonglong2* qv = (const ulonglong2*)(sq + q * 8);
        const ulonglong2 t0 = qv[0];
        const ulonglong2 t1 = qv[1];
        const ulonglong2 t2 = qv[2];
        const ulonglong2 t3 = qv[3];
        const unsigned long long b0 = t0.x, b1 = t0.y;
        const unsigned long long b2 = t1.x, b3 = t1.y;
        const unsigned long long b4 = t2.x, b5 = t2.y;
        const unsigned long long A2 = t3.x, Dn2 = t3.y;

        ulonglong2 rr;
#pragma unroll
        for (int p = 0; p < 2; ++p) {
            const unsigned long long cc = f32x2_fma(lab2[p], Dn2, A2);  // independent, issues early
            const unsigned long long a0 = abs2(f32x2_add(b0, ntb[p][0]));
            const unsigned long long a1 = abs2(f32x2_add(b1, ntb[p][1]));
            const unsigned long long a2 = abs2(f32x2_add(b2, ntb[p][2]));
            const unsigned long long a3 = abs2(f32x2_add(b3, ntb[p][3]));
            const unsigned long long a4 = abs2(f32x2_add(b4, ntb[p][4]));
            const unsigned long long a5 = abs2(f32x2_add(b5, ntb[p][5]));
            // balanced tree, cc folded into one branch (depth 3, 7 adds + 1 fma total w/ diffs)
            const unsigned long long s = f32x2_add(
                f32x2_add(f32x2_add(a0, a1), f32x2_add(a2, a3)),
                f32x2_add(f32x2_add(a4, a5), cc));
            if (p == 0) rr.x = s; else rr.y = s;
        }
        *(ulonglong2*)(obase + q * 4096) = rr;   // STG.128 straight from packed pairs
    }
}

extern "C" void kernel_launch(void* const* d_in, const int* in_sizes, int n_in,
                              void* d_out, int out_size)
{
    const float* logits  = (const float*)d_in[0];  // (16, 2048, 2) f32
    const float* qboxes  = (const float*)d_in[1];  // (16, 2048, 6) f32
    const int*   tlabels = (const int*)  d_in[2];  // (1024,) int32
    const float* tboxes  = (const float*)d_in[3];  // (1024, 6) f32

    const int total_q = 16 * 2048;
    hm_cost_kernel<<<total_q / QB, THREADS>>>(logits, qboxes, tlabels, tboxes, (float*)d_out);
}